// round 10
// baseline (speedup 1.0000x reference)
#include <cuda_runtime.h>
#include <cuda_fp16.h>
#include <stdint.h>

// ============================================================================
// GConvGRU (K=1 Cheb, H0=0) collapses to:
//   Z  = sigmoid(x@Wxz + bxz + bhz)
//   Ht = tanh   (x@Wxh + bxh + bhh)
//   h  = elu((1-Z)*Ht)
//   out = h@Wlin + blin
// sm_100 toolchain (no tcgen05). Fused fp16 mma.sync (m16n8k16) + ldmatrix.
// 512 threads / 16 warps (4m x 4n) per 128-row tile. N processed in quarters
// of 64: weight quarter resident in smem, FULL K=256 MMA loop with no
// internal barriers; next quarter's weights prefetched to registers during
// the MMA run. Readout double-buffers Wl quarters (1 sync/quarter).
// ============================================================================

#define M_NODES 100000
#define CH      256
#define MT      128
#define NTILES  782
#define THREADS 512

#define XSTRIDE 528               // 33 x 16B units -> ldmatrix conflict-free
#define WMAT    33792             // 64 rows x 528 B per weight-quarter matrix

#define OFF_BZ  0
#define OFF_BH  1024
#define OFF_BL  2048
#define OFF_X   3072
#define OFF_H   (OFF_X + 128 * XSTRIDE)        // 70656
#define OFF_W   (OFF_H + 128 * XSTRIDE)        // 138240 ; 2 x WMAT
#define SMEM_TOTAL (OFF_W + 2 * WMAT)          // 205824 B

#define L2E 1.4426950408889634f

static __device__ __half g_wt[3 * CH * CH];    // n-major fp16: [w][n][k]

// ---------------------------------------------------------------------------
__device__ __forceinline__ uint32_t smem_u32(const void* p) {
    uint32_t a;
    asm("{ .reg .u64 t; cvta.to.shared.u64 t, %1; cvt.u32.u64 %0, t; }"
        : "=r"(a) : "l"(p));
    return a;
}
__device__ __forceinline__ float fex2(float x) {
    float y; asm("ex2.approx.f32 %0, %1;" : "=f"(y) : "f"(x)); return y;
}
__device__ __forceinline__ float frcp(float x) {
    float y; asm("rcp.approx.f32 %0, %1;" : "=f"(y) : "f"(x)); return y;
}
__device__ __forceinline__ void ldsm4(uint32_t r[4], uint32_t addr) {
    asm volatile("ldmatrix.sync.aligned.m8n8.x4.shared.b16 {%0,%1,%2,%3}, [%4];"
                 : "=r"(r[0]), "=r"(r[1]), "=r"(r[2]), "=r"(r[3]) : "r"(addr));
}
__device__ __forceinline__ void mma16(float c[4], const uint32_t a[4],
                                      uint32_t b0, uint32_t b1) {
    asm volatile(
        "mma.sync.aligned.m16n8k16.row.col.f32.f16.f16.f32 "
        "{%0,%1,%2,%3}, {%4,%5,%6,%7}, {%8,%9}, {%0,%1,%2,%3};"
        : "+f"(c[0]), "+f"(c[1]), "+f"(c[2]), "+f"(c[3])
        : "r"(a[0]), "r"(a[1]), "r"(a[2]), "r"(a[3]), "r"(b0), "r"(b1));
}
__device__ __forceinline__ uint32_t packh2(float a, float b) {
    __half2 h = __floats2half2_rn(a, b);
    return *reinterpret_cast<uint32_t*>(&h);
}

// ---------------------------------------------------------------------------
// Prep: Wt[n][k] = fp16(W[k][n]) for Wxz, Wxh, Wlin (n-major)
// ---------------------------------------------------------------------------
__global__ void prep_kernel(const float* __restrict__ Wz,
                            const float* __restrict__ Wh,
                            const float* __restrict__ Wl) {
    __shared__ float t[32][33];
    const float* W = (blockIdx.z == 0) ? Wz : (blockIdx.z == 1) ? Wh : Wl;
    __half* Wt = g_wt + (size_t)blockIdx.z * CH * CH;
    int n0 = blockIdx.x * 32, k0 = blockIdx.y * 32;
    int tx = threadIdx.x, ty = threadIdx.y;   // 32 x 8
#pragma unroll
    for (int r = 0; r < 4; r++)
        t[ty + r * 8][tx] = W[(size_t)(k0 + ty + r * 8) * CH + n0 + tx];
    __syncthreads();
#pragma unroll
    for (int r = 0; r < 4; r++)
        Wt[(size_t)(n0 + ty + r * 8) * CH + k0 + tx] =
            __float2half_rn(t[tx][ty + r * 8]);
}

// ---------------------------------------------------------------------------
// Fused main kernel: one CTA per 128-row tile, 16 warps (4m x 4n)
// ---------------------------------------------------------------------------
__global__ void __launch_bounds__(THREADS, 1) fused_kernel(
    const float* __restrict__ x,
    const float* __restrict__ bxz, const float* __restrict__ bhz,
    const float* __restrict__ bxh, const float* __restrict__ bhh,
    const float* __restrict__ blin,
    float* __restrict__ out)
{
    extern __shared__ char smem[];
    const uint32_t sbase = smem_u32(smem);
    const int tid = threadIdx.x, wid = tid >> 5, lane = tid & 31;
    const int grp = lane >> 2, t4 = lane & 3;
    const int wm = wid & 3, wn = wid >> 2;      // 4m x 4n
    const int wr = wm * 32;
    const int mbase = blockIdx.x * MT;

    float* bzs = (float*)(smem + OFF_BZ);
    float* bhs = (float*)(smem + OFF_BH);
    float* bls = (float*)(smem + OFF_BL);
    if (tid < CH) {
        bzs[tid] = bxz[tid] + bhz[tid];
        bhs[tid] = bxh[tid] + bhh[tid];
        bls[tid] = blin[tid];
    }

    const __half* wtz = g_wt;
    const __half* wth = g_wt + CH * CH;
    const __half* wtl = g_wt + 2 * CH * CH;

    // staging map: idx -> (row = idx>>5, 16B-chunk c = idx&31); 4 idx/thread
    const int srow[4] = { (0 * THREADS + tid) >> 5, (1 * THREADS + tid) >> 5,
                          (2 * THREADS + tid) >> 5, (3 * THREADS + tid) >> 5 };
    const int scol = tid & 31;   // idx&31 is invariant across i (THREADS%32==0)

    uint4 pz[4], ph[4];
    auto ldgW = [&](int q) {
#pragma unroll
        for (int i = 0; i < 4; i++) {
            const __half* p = wtz + (size_t)(q * 64 + srow[i]) * CH + scol * 8;
            pz[i] = *(const uint4*)(p);
            ph[i] = *(const uint4*)(p + CH * CH);
        }
    };
    auto stsW = [&]() {
#pragma unroll
        for (int i = 0; i < 4; i++) {
            int o = srow[i] * XSTRIDE + scol * 16;
            *(uint4*)(smem + OFF_W + o) = pz[i];
            *(uint4*)(smem + OFF_W + WMAT + o) = ph[i];
        }
    };

    ldgW(0);

    // ---- stage X tile (fp32 -> fp16, resident) ----
#pragma unroll
    for (int i = 0; i < 8; i++) {
        int idx = i * THREADS + tid;
        int r = idx >> 5, c16 = idx & 31;
        int gr = mbase + r;
        float4 v0 = make_float4(0.f, 0.f, 0.f, 0.f), v1 = v0;
        if (gr < M_NODES) {
            const float* p = x + (size_t)gr * CH + c16 * 8;
            v0 = *(const float4*)(p);
            v1 = *(const float4*)(p + 4);
        }
        uint4 u = make_uint4(packh2(v0.x, v0.y), packh2(v0.z, v0.w),
                             packh2(v1.x, v1.y), packh2(v1.z, v1.w));
        *(uint4*)(smem + OFF_X + r * XSTRIDE + c16 * 16) = u;
    }
    stsW();
    __syncthreads();

    // per-lane ldmatrix base addresses
    const uint32_t xa = sbase + OFF_X + (uint32_t)(wr + (lane & 15)) * XSTRIDE
                        + ((lane >> 4) << 4);
    const uint32_t ha = sbase + OFF_H + (uint32_t)(wr + (lane & 15)) * XSTRIDE
                        + ((lane >> 4) << 4);
    const uint32_t wb = sbase + OFF_W + (uint32_t)(wn * 16 + (lane & 15)) * XSTRIDE
                        + ((lane >> 4) << 4);

    // ======================= gates: four N-quarters ====================
#pragma unroll 1
    for (int q = 0; q < 4; q++) {
        if (q < 3) ldgW(q + 1);

        float az[2][2][4], ah[2][2][4];
#pragma unroll
        for (int i = 0; i < 2; i++)
#pragma unroll
            for (int j = 0; j < 2; j++)
#pragma unroll
                for (int k = 0; k < 4; k++) { az[i][j][k] = 0.f; ah[i][j][k] = 0.f; }

        // full K=256, no internal barriers
#pragma unroll
        for (int ks = 0; ks < 16; ks++) {
            uint32_t a0[4], a1[4], bz4[4], bh4[4];
            ldsm4(a0, xa + ks * 32);
            ldsm4(a1, xa + 16 * XSTRIDE + ks * 32);
            ldsm4(bz4, wb + ks * 32);
            ldsm4(bh4, wb + WMAT + ks * 32);
            mma16(az[0][0], a0, bz4[0], bz4[2]);
            mma16(az[1][0], a1, bz4[0], bz4[2]);
            mma16(az[0][1], a0, bz4[1], bz4[3]);
            mma16(az[1][1], a1, bz4[1], bz4[3]);
            mma16(ah[0][0], a0, bh4[0], bh4[2]);
            mma16(ah[1][0], a1, bh4[0], bh4[2]);
            mma16(ah[0][1], a0, bh4[1], bh4[3]);
            mma16(ah[1][1], a1, bh4[1], bh4[3]);
        }

        // ---- GRU/elu epilogue -> H quarter (fp16 smem) ----
#pragma unroll
        for (int mi = 0; mi < 2; mi++) {
#pragma unroll
            for (int nt = 0; nt < 2; nt++) {
                int col = q * 64 + wn * 16 + nt * 8 + 2 * t4;
                float bz0 = bzs[col], bz1 = bzs[col + 1];
                float bh0 = bhs[col], bh1 = bhs[col + 1];
#pragma unroll
                for (int hh = 0; hh < 2; hh++) {
                    int row = wr + mi * 16 + grp + hh * 8;
                    float a0 = az[mi][nt][2 * hh + 0] + bz0;
                    float a1 = az[mi][nt][2 * hh + 1] + bz1;
                    float c0 = ah[mi][nt][2 * hh + 0] + bh0;
                    float c1 = ah[mi][nt][2 * hh + 1] + bh1;
                    float zp0 = frcp(1.f + fex2(a0 * L2E));      // 1 - sigmoid
                    float zp1 = frcp(1.f + fex2(a1 * L2E));
                    float t0 = 1.f - 2.f * frcp(fex2(c0 * (2.f * L2E)) + 1.f);
                    float t1 = 1.f - 2.f * frcp(fex2(c1 * (2.f * L2E)) + 1.f);
                    float v0 = zp0 * t0, v1 = zp1 * t1;
                    v0 = (v0 > 0.f) ? v0 : (fex2(v0 * L2E) - 1.f);
                    v1 = (v1 > 0.f) ? v1 : (fex2(v1 * L2E) - 1.f);
                    *(uint32_t*)(smem + OFF_H + row * XSTRIDE + col * 2) =
                        packh2(v0, v1);
                }
            }
        }
        __syncthreads();              // all warps done reading W quarter
        if (q < 3) { stsW(); __syncthreads(); }
    }

    // ======================= readout: out = H @ WlT + bl ===============
    {
        uint4 pl[4];
        auto ldgL = [&](int q) {
#pragma unroll
            for (int i = 0; i < 4; i++)
                pl[i] = *(const uint4*)(wtl + (size_t)(q * 64 + srow[i]) * CH
                                        + scol * 8);
        };
        auto stsL = [&](int b) {
#pragma unroll
            for (int i = 0; i < 4; i++)
                *(uint4*)(smem + OFF_W + b * WMAT + srow[i] * XSTRIDE
                          + scol * 16) = pl[i];
        };

        ldgL(0); stsL(0);
        __syncthreads();

#pragma unroll 1
        for (int q = 0; q < 4; q++) {
            if (q < 3) ldgL(q + 1);

            float o[2][2][4];
#pragma unroll
            for (int i = 0; i < 2; i++)
#pragma unroll
                for (int j = 0; j < 2; j++)
#pragma unroll
                    for (int k = 0; k < 4; k++) o[i][j][k] = 0.f;

            const uint32_t wbq = wb + (uint32_t)(q & 1) * WMAT;
#pragma unroll
            for (int ks = 0; ks < 16; ks++) {
                uint32_t a0[4], a1[4], b4[4];
                ldsm4(a0, ha + ks * 32);
                ldsm4(a1, ha + 16 * XSTRIDE + ks * 32);
                ldsm4(b4, wbq + ks * 32);
                mma16(o[0][0], a0, b4[0], b4[2]);
                mma16(o[1][0], a1, b4[0], b4[2]);
                mma16(o[0][1], a0, b4[1], b4[3]);
                mma16(o[1][1], a1, b4[1], b4[3]);
            }

            // ---- biased store ----
#pragma unroll
            for (int mi = 0; mi < 2; mi++) {
#pragma unroll
                for (int nt = 0; nt < 2; nt++) {
                    int col = q * 64 + wn * 16 + nt * 8 + 2 * t4;
                    float b0 = bls[col], b1 = bls[col + 1];
#pragma unroll
                    for (int hh = 0; hh < 2; hh++) {
                        int gr = mbase + wr + mi * 16 + grp + hh * 8;
                        if (gr < M_NODES) {
                            *(float2*)(out + (size_t)gr * CH + col) =
                                make_float2(o[mi][nt][2 * hh + 0] + b0,
                                            o[mi][nt][2 * hh + 1] + b1);
                        }
                    }
                }
            }
            if (q < 3) {
                stsL((q + 1) & 1);    // other buffer: no pre-sync needed
                __syncthreads();      // buffer ready before next MMA
            }
        }
    }
}

// ---------------------------------------------------------------------------
extern "C" void kernel_launch(void* const* d_in, const int* in_sizes, int n_in,
                              void* d_out, int out_size)
{
    const float* x     = (const float*)d_in[0];
    const float* W_xz  = (const float*)d_in[3];
    const float* b_xz  = (const float*)d_in[4];
    const float* b_hz  = (const float*)d_in[6];
    const float* W_xh  = (const float*)d_in[11];
    const float* b_xh  = (const float*)d_in[12];
    const float* b_hh  = (const float*)d_in[14];
    const float* W_lin = (const float*)d_in[15];
    const float* b_lin = (const float*)d_in[16];
    float* out = (float*)d_out;

    static bool attr_done = false;
    if (!attr_done) {
        (void)cudaFuncSetAttribute(fused_kernel,
                                   cudaFuncAttributeMaxDynamicSharedMemorySize,
                                   SMEM_TOTAL);
        attr_done = true;
    }

    prep_kernel<<<dim3(8, 8, 3), dim3(32, 8)>>>(W_xz, W_xh, W_lin);
    fused_kernel<<<NTILES, THREADS, SMEM_TOTAL>>>(x, b_xz, b_hz, b_xh, b_hh,
                                                  b_lin, out);
}

// round 11
// speedup vs baseline: 1.1113x; 1.1113x over previous
#include <cuda_runtime.h>
#include <cuda_fp16.h>
#include <stdint.h>

// ============================================================================
// GConvGRU (K=1 Cheb, H0=0) collapses to:
//   Z  = sigmoid(x@Wxz + bxz + bhz)
//   Ht = tanh   (x@Wxh + bxh + bhh)
//   h  = elu((1-Z)*Ht)
//   out = h@Wlin + blin
// sm_100 toolchain (no tcgen05). Fused fp16 mma.sync (m16n8k16) + ldmatrix.
// MT=64 rows/CTA, 256 threads (8 warps, 2m x 4n), 2 CTAs/SM so independent
// CTAs overlap each other's staging/epilogue/barrier phases. Weight staging
// via cp.async (no register cost). Gates GEMM in two N-halves with
// double-buffered K-chunks; GRU/elu epilogue -> H fp16 smem; readout GEMM;
// biased fp32 store. Weights pre-transposed to N-major fp16 by prep kernel.
// ============================================================================

#define M_NODES 100000
#define CH      256
#define MT      64
#define NTILES  1563              // ceil(100000/64)
#define THREADS 256

#define XSTRIDE 528               // 33 x 16B units -> ldmatrix conflict-free
#define WSTRIDE 80                // 5 x 16B units  -> ldmatrix conflict-free
#define WBUF    20480             // gates: [z 10240 | h 10240]; readout: 256 rows

#define OFF_BZ  0
#define OFF_BH  1024
#define OFF_BL  2048
#define OFF_X   3072
#define OFF_H   (OFF_X + MT * XSTRIDE)   // 36864
#define OFF_W   (OFF_H + MT * XSTRIDE)   // 70656 ; 2 x WBUF
#define SMEM_TOTAL (OFF_W + 2 * WBUF)    // 111616 B -> 2 CTAs/SM

#define L2E 1.4426950408889634f

static __device__ __half g_wt[3 * CH * CH];    // n-major fp16: [w][n][k]

// ---------------------------------------------------------------------------
__device__ __forceinline__ uint32_t smem_u32(const void* p) {
    uint32_t a;
    asm("{ .reg .u64 t; cvta.to.shared.u64 t, %1; cvt.u32.u64 %0, t; }"
        : "=r"(a) : "l"(p));
    return a;
}
__device__ __forceinline__ float fex2(float x) {
    float y; asm("ex2.approx.f32 %0, %1;" : "=f"(y) : "f"(x)); return y;
}
__device__ __forceinline__ float frcp(float x) {
    float y; asm("rcp.approx.f32 %0, %1;" : "=f"(y) : "f"(x)); return y;
}
__device__ __forceinline__ void cpa16(uint32_t s, const void* g) {
    asm volatile("cp.async.ca.shared.global [%0], [%1], 16;"
                 :: "r"(s), "l"(g) : "memory");
}
#define CP_COMMIT() asm volatile("cp.async.commit_group;" ::: "memory")
#define CP_WAIT0()  asm volatile("cp.async.wait_group 0;" ::: "memory")

__device__ __forceinline__ void ldsm4(uint32_t r[4], uint32_t addr) {
    asm volatile("ldmatrix.sync.aligned.m8n8.x4.shared.b16 {%0,%1,%2,%3}, [%4];"
                 : "=r"(r[0]), "=r"(r[1]), "=r"(r[2]), "=r"(r[3]) : "r"(addr));
}
__device__ __forceinline__ void mma16(float c[4], const uint32_t a[4],
                                      uint32_t b0, uint32_t b1) {
    asm volatile(
        "mma.sync.aligned.m16n8k16.row.col.f32.f16.f16.f32 "
        "{%0,%1,%2,%3}, {%4,%5,%6,%7}, {%8,%9}, {%0,%1,%2,%3};"
        : "+f"(c[0]), "+f"(c[1]), "+f"(c[2]), "+f"(c[3])
        : "r"(a[0]), "r"(a[1]), "r"(a[2]), "r"(a[3]), "r"(b0), "r"(b1));
}
__device__ __forceinline__ uint32_t packh2(float a, float b) {
    __half2 h = __floats2half2_rn(a, b);
    return *reinterpret_cast<uint32_t*>(&h);
}

// ---------------------------------------------------------------------------
// Prep: Wt[n][k] = fp16(W[k][n]) for Wxz, Wxh, Wlin (n-major)
// ---------------------------------------------------------------------------
__global__ void prep_kernel(const float* __restrict__ Wz,
                            const float* __restrict__ Wh,
                            const float* __restrict__ Wl) {
    __shared__ float t[32][33];
    const float* W = (blockIdx.z == 0) ? Wz : (blockIdx.z == 1) ? Wh : Wl;
    __half* Wt = g_wt + (size_t)blockIdx.z * CH * CH;
    int n0 = blockIdx.x * 32, k0 = blockIdx.y * 32;
    int tx = threadIdx.x, ty = threadIdx.y;   // 32 x 8
#pragma unroll
    for (int r = 0; r < 4; r++)
        t[ty + r * 8][tx] = W[(size_t)(k0 + ty + r * 8) * CH + n0 + tx];
    __syncthreads();
#pragma unroll
    for (int r = 0; r < 4; r++)
        Wt[(size_t)(n0 + ty + r * 8) * CH + k0 + tx] =
            __float2half_rn(t[tx][ty + r * 8]);
}

// ---------------------------------------------------------------------------
// Fused main kernel: one CTA per 64-row tile, 8 warps (2m x 4n), 2 CTAs/SM
// ---------------------------------------------------------------------------
__global__ void __launch_bounds__(THREADS, 2) fused_kernel(
    const float* __restrict__ x,
    const float* __restrict__ bxz, const float* __restrict__ bhz,
    const float* __restrict__ bxh, const float* __restrict__ bhh,
    const float* __restrict__ blin,
    float* __restrict__ out)
{
    extern __shared__ char smem[];
    const uint32_t sbase = smem_u32(smem);
    const int tid = threadIdx.x, wid = tid >> 5, lane = tid & 31;
    const int grp = lane >> 2, t4 = lane & 3;
    const int wm = wid & 1, wn = wid >> 1;      // 2m x 4n
    const int wr = wm * 32;
    const int mbase = blockIdx.x * MT;

    float* bzs = (float*)(smem + OFF_BZ);
    float* bhs = (float*)(smem + OFF_BH);
    float* bls = (float*)(smem + OFF_BL);
    bzs[tid] = bxz[tid] + bhz[tid];
    bhs[tid] = bxh[tid] + bhh[tid];
    bls[tid] = blin[tid];

    const __half* wtz = g_wt;
    const __half* wtl = g_wt + 2 * CH * CH;

    // ---- weight staging via cp.async ----
    // gates: Bz/Bh half-chunk = 128 rows x 64B (4 x 16B); 512 xfers/matrix
    auto cpW = [&](int nh, int ch, int buf) {
#pragma unroll
        for (int i = 0; i < 2; i++) {
            int idx = i * THREADS + tid;       // 0..511
            int row = idx >> 2, u = idx & 3;
            const __half* gz = wtz + (size_t)(nh * 128 + row) * CH + ch * 32 + u * 8;
            uint32_t s = sbase + OFF_W + buf * WBUF + row * WSTRIDE + u * 16;
            cpa16(s, gz);
            cpa16(s + 10240, gz + CH * CH);    // Wxh
        }
    };
    // readout: Wl chunk = 256 rows x 64B; 1024 xfers
    auto cpL = [&](int ch, int buf) {
#pragma unroll
        for (int i = 0; i < 4; i++) {
            int idx = i * THREADS + tid;       // 0..1023
            int row = idx >> 2, u = idx & 3;
            cpa16(sbase + OFF_W + buf * WBUF + row * WSTRIDE + u * 16,
                  wtl + (size_t)row * CH + ch * 32 + u * 8);
        }
    };

    // ---- stage X tile (fp32 -> fp16, resident) ----
#pragma unroll
    for (int i = 0; i < 8; i++) {
        int idx = i * THREADS + tid;           // 0..2047
        int r = idx >> 5, c16 = idx & 31;
        int gr = mbase + r;
        float4 v0 = make_float4(0.f, 0.f, 0.f, 0.f), v1 = v0;
        if (gr < M_NODES) {
            const float* p = x + (size_t)gr * CH + c16 * 8;
            v0 = *(const float4*)(p);
            v1 = *(const float4*)(p + 4);
        }
        uint4 u = make_uint4(packh2(v0.x, v0.y), packh2(v0.z, v0.w),
                             packh2(v1.x, v1.y), packh2(v1.z, v1.w));
        *(uint4*)(smem + OFF_X + r * XSTRIDE + c16 * 16) = u;
    }

    // per-lane ldmatrix base addresses
    const uint32_t xa = sbase + OFF_X + (uint32_t)(wr + (lane & 15)) * XSTRIDE
                        + ((lane >> 4) << 4);
    const uint32_t ha = sbase + OFF_H + (uint32_t)(wr + (lane & 15)) * XSTRIDE
                        + ((lane >> 4) << 4);
    const uint32_t wbG = sbase + OFF_W + (uint32_t)(wn * 32 + (lane & 15)) * WSTRIDE
                         + ((lane >> 4) << 4);
    const uint32_t wbL = sbase + OFF_W + (uint32_t)(wn * 64 + (lane & 15)) * WSTRIDE
                         + ((lane >> 4) << 4);

    // ======================= gates: two N-halves =======================
#pragma unroll 1
    for (int nh = 0; nh < 2; nh++) {
        cpW(nh, 0, 0); CP_COMMIT();

        float az[2][4][4], ah[2][4][4];
#pragma unroll
        for (int i = 0; i < 2; i++)
#pragma unroll
            for (int j = 0; j < 4; j++)
#pragma unroll
                for (int k = 0; k < 4; k++) { az[i][j][k] = 0.f; ah[i][j][k] = 0.f; }

        CP_WAIT0();
        __syncthreads();           // X (first nh) + W chunk 0 ready
#pragma unroll 1
        for (int ch = 0; ch < 8; ch++) {
            const int buf = ch & 1;
            if (ch < 7) { cpW(nh, ch + 1, buf ^ 1); CP_COMMIT(); }
#pragma unroll
            for (int ks = 0; ks < 2; ks++) {
                uint32_t a0[4], a1[4];
                ldsm4(a0, xa + ch * 64 + ks * 32);
                ldsm4(a1, xa + 16 * XSTRIDE + ch * 64 + ks * 32);
#pragma unroll
                for (int pp = 0; pp < 2; pp++) {
                    uint32_t bz[4], bh[4];
                    uint32_t bo = wbG + buf * WBUF + pp * 16 * WSTRIDE + ks * 32;
                    ldsm4(bz, bo);
                    ldsm4(bh, bo + 10240);
                    mma16(az[0][2 * pp],     a0, bz[0], bz[2]);
                    mma16(az[1][2 * pp],     a1, bz[0], bz[2]);
                    mma16(az[0][2 * pp + 1], a0, bz[1], bz[3]);
                    mma16(az[1][2 * pp + 1], a1, bz[1], bz[3]);
                    mma16(ah[0][2 * pp],     a0, bh[0], bh[2]);
                    mma16(ah[1][2 * pp],     a1, bh[0], bh[2]);
                    mma16(ah[0][2 * pp + 1], a0, bh[1], bh[3]);
                    mma16(ah[1][2 * pp + 1], a1, bh[1], bh[3]);
                }
            }
            if (ch < 7) { CP_WAIT0(); __syncthreads(); }
        }

        // ---- GRU/elu epilogue -> H half (fp16 smem) ----
#pragma unroll
        for (int mi = 0; mi < 2; mi++) {
#pragma unroll
            for (int p = 0; p < 4; p++) {
                int col = nh * 128 + wn * 32 + p * 8 + 2 * t4;
                float bz0 = bzs[col], bz1 = bzs[col + 1];
                float bh0 = bhs[col], bh1 = bhs[col + 1];
#pragma unroll
                for (int hh = 0; hh < 2; hh++) {
                    int row = wr + mi * 16 + grp + hh * 8;
                    float a0 = az[mi][p][2 * hh + 0] + bz0;
                    float a1 = az[mi][p][2 * hh + 1] + bz1;
                    float c0 = ah[mi][p][2 * hh + 0] + bh0;
                    float c1 = ah[mi][p][2 * hh + 1] + bh1;
                    float zp0 = frcp(1.f + fex2(a0 * L2E));      // 1 - sigmoid
                    float zp1 = frcp(1.f + fex2(a1 * L2E));
                    float t0 = 1.f - 2.f * frcp(fex2(c0 * (2.f * L2E)) + 1.f);
                    float t1 = 1.f - 2.f * frcp(fex2(c1 * (2.f * L2E)) + 1.f);
                    float v0 = zp0 * t0, v1 = zp1 * t1;
                    v0 = (v0 > 0.f) ? v0 : (fex2(v0 * L2E) - 1.f);
                    v1 = (v1 > 0.f) ? v1 : (fex2(v1 * L2E) - 1.f);
                    *(uint32_t*)(smem + OFF_H + row * XSTRIDE + col * 2) =
                        packh2(v0, v1);
                }
            }
        }
        // no sync needed here: next writes target the buffer whose reads were
        // fenced at ch==6; the next phase's CP_WAIT0+sync orders everything.
    }

    // ======================= readout: out = H @ WlT + bl ===============
    {
        cpL(0, 0); CP_COMMIT();

        float o[2][8][4];
#pragma unroll
        for (int i = 0; i < 2; i++)
#pragma unroll
            for (int j = 0; j < 8; j++)
#pragma unroll
                for (int k = 0; k < 4; k++) o[i][j][k] = 0.f;

        CP_WAIT0();
        __syncthreads();           // H complete + Wl chunk 0 ready
#pragma unroll 1
        for (int ch = 0; ch < 8; ch++) {
            const int buf = ch & 1;
            if (ch < 7) { cpL(ch + 1, buf ^ 1); CP_COMMIT(); }
#pragma unroll
            for (int ks = 0; ks < 2; ks++) {
                uint32_t a0[4], a1[4];
                ldsm4(a0, ha + ch * 64 + ks * 32);
                ldsm4(a1, ha + 16 * XSTRIDE + ch * 64 + ks * 32);
#pragma unroll
                for (int pp = 0; pp < 4; pp++) {
                    uint32_t b4[4];
                    ldsm4(b4, wbL + buf * WBUF + pp * 16 * WSTRIDE + ks * 32);
                    mma16(o[0][2 * pp],     a0, b4[0], b4[2]);
                    mma16(o[1][2 * pp],     a1, b4[0], b4[2]);
                    mma16(o[0][2 * pp + 1], a0, b4[1], b4[3]);
                    mma16(o[1][2 * pp + 1], a1, b4[1], b4[3]);
                }
            }
            if (ch < 7) { CP_WAIT0(); __syncthreads(); }
        }

        // ---- biased store ----
#pragma unroll
        for (int mi = 0; mi < 2; mi++) {
#pragma unroll
            for (int p = 0; p < 8; p++) {
                int col = wn * 64 + p * 8 + 2 * t4;
                float b0 = bls[col], b1 = bls[col + 1];
#pragma unroll
                for (int hh = 0; hh < 2; hh++) {
                    int gr = mbase + wr + mi * 16 + grp + hh * 8;
                    if (gr < M_NODES) {
                        *(float2*)(out + (size_t)gr * CH + col) =
                            make_float2(o[mi][p][2 * hh + 0] + b0,
                                        o[mi][p][2 * hh + 1] + b1);
                    }
                }
            }
        }
    }
}

// ---------------------------------------------------------------------------
extern "C" void kernel_launch(void* const* d_in, const int* in_sizes, int n_in,
                              void* d_out, int out_size)
{
    const float* x     = (const float*)d_in[0];
    const float* W_xz  = (const float*)d_in[3];
    const float* b_xz  = (const float*)d_in[4];
    const float* b_hz  = (const float*)d_in[6];
    const float* W_xh  = (const float*)d_in[11];
    const float* b_xh  = (const float*)d_in[12];
    const float* b_hh  = (const float*)d_in[14];
    const float* W_lin = (const float*)d_in[15];
    const float* b_lin = (const float*)d_in[16];
    float* out = (float*)d_out;

    static bool attr_done = false;
    if (!attr_done) {
        (void)cudaFuncSetAttribute(fused_kernel,
                                   cudaFuncAttributeMaxDynamicSharedMemorySize,
                                   SMEM_TOTAL);
        attr_done = true;
    }

    prep_kernel<<<dim3(8, 8, 3), dim3(32, 8)>>>(W_xz, W_xh, W_lin);
    fused_kernel<<<NTILES, THREADS, SMEM_TOTAL>>>(x, b_xz, b_hz, b_xh, b_hh,
                                                  b_lin, out);
}